// round 1
// baseline (speedup 1.0000x reference)
#include <cuda_runtime.h>
#include <cstdint>

#define N_NODES 4096
#define IN_FEAT 512
#define EMBED   512
#define HEADS   8
#define HEAD_DIM 64
#define E3      1536   // Q|K|V concatenated

// ---------------- scratch (static device globals: no allocation) ------------
__device__ float g_QKV[N_NODES * E3];     // [n][0:512)=Q, [512:1024)=K, [1024:1536)=V
__device__ int   g_argmax[HEADS * N_NODES];

// ---------------- packed fp32x2 helpers (sm_103a) ---------------------------
__device__ __forceinline__ unsigned long long pack2(float lo, float hi) {
    unsigned long long r;
    asm("mov.b64 %0, {%1, %2};" : "=l"(r) : "f"(lo), "f"(hi));
    return r;
}
__device__ __forceinline__ void unpack2(unsigned long long v, float& lo, float& hi) {
    asm("mov.b64 {%0, %1}, %2;" : "=f"(lo), "=f"(hi) : "l"(v));
}
__device__ __forceinline__ unsigned long long fma2(unsigned long long a,
                                                   unsigned long long b,
                                                   unsigned long long c) {
    unsigned long long d;
    asm("fma.rn.f32x2 %0, %1, %2, %3;" : "=l"(d) : "l"(a), "l"(b), "l"(c));
    return d;
}
__device__ __forceinline__ unsigned long long add2(unsigned long long a,
                                                   unsigned long long b) {
    unsigned long long d;
    asm("add.rn.f32x2 %0, %1, %2;" : "=l"(d) : "l"(a), "l"(b));
    return d;
}

// ============================================================================
// Kernel 1: fused QKV projection.  C[4096,1536] = x[4096,512] @ Wcat^T
// Block tile 128(m) x 64(n) x 16(k); 256 threads; 8x4 micro-tile in f32x2.
// ============================================================================
__global__ __launch_bounds__(256, 1) void qkv_gemm(
    const float* __restrict__ x,
    const float* __restrict__ WQ,
    const float* __restrict__ WK,
    const float* __restrict__ WV)
{
    __shared__ float As[16][132];   // [k][m], padded
    __shared__ float Bs[16][68];    // [k][n], padded

    const int tid = threadIdx.x;
    const int tx  = tid & 15;       // n direction (16 * 4 = 64)
    const int ty  = tid >> 4;       // m direction (16 * 8 = 128)
    const int m0  = blockIdx.y * 128;
    const int n0  = blockIdx.x * 64;           // 0..1472
    const float* W = (n0 < 512) ? WQ : ((n0 < 1024) ? WK : WV);
    const int wn0 = n0 & 511;

    unsigned long long c2[8][2];
#pragma unroll
    for (int i = 0; i < 8; i++) { c2[i][0] = 0ULL; c2[i][1] = 0ULL; }

    for (int k0 = 0; k0 < IN_FEAT; k0 += 16) {
        // load A tile (128 x 16), transposed into As[k][m]
#pragma unroll
        for (int it = 0; it < 2; it++) {
            int idx = it * 256 + tid;
            int row = idx >> 2;          // 0..127
            int c4  = idx & 3;           // 0..3 (float4 within 16 cols)
            float4 v = *(const float4*)&x[(m0 + row) * IN_FEAT + k0 + c4 * 4];
            As[c4 * 4 + 0][row] = v.x;
            As[c4 * 4 + 1][row] = v.y;
            As[c4 * 4 + 2][row] = v.z;
            As[c4 * 4 + 3][row] = v.w;
        }
        // load B tile (64 x 16), transposed into Bs[k][n]
        {
            int row = tid >> 2;          // 0..63
            int c4  = tid & 3;
            float4 v = *(const float4*)&W[(wn0 + row) * IN_FEAT + k0 + c4 * 4];
            Bs[c4 * 4 + 0][row] = v.x;
            Bs[c4 * 4 + 1][row] = v.y;
            Bs[c4 * 4 + 2][row] = v.z;
            Bs[c4 * 4 + 3][row] = v.w;
        }
        __syncthreads();

#pragma unroll
        for (int k = 0; k < 16; k++) {
            float4 b  = *(const float4*)&Bs[k][tx * 4];
            unsigned long long b01 = pack2(b.x, b.y);
            unsigned long long b23 = pack2(b.z, b.w);
            float4 a0 = *(const float4*)&As[k][ty * 8];
            float4 a1 = *(const float4*)&As[k][ty * 8 + 4];
            float av[8] = {a0.x, a0.y, a0.z, a0.w, a1.x, a1.y, a1.z, a1.w};
#pragma unroll
            for (int i = 0; i < 8; i++) {
                unsigned long long aa = pack2(av[i], av[i]);
                c2[i][0] = fma2(aa, b01, c2[i][0]);
                c2[i][1] = fma2(aa, b23, c2[i][1]);
            }
        }
        __syncthreads();
    }

#pragma unroll
    for (int i = 0; i < 8; i++) {
        float o0, o1, o2, o3;
        unpack2(c2[i][0], o0, o1);
        unpack2(c2[i][1], o2, o3);
        float4 v = make_float4(o0, o1, o2, o3);
        *(float4*)&g_QKV[(m0 + ty * 8 + i) * E3 + n0 + tx * 4] = v;
    }
}

// ============================================================================
// Kernel 2: masked score argmax.
// Block = 32 queries x all 8 heads. warp w = head w, lane = local query.
// Q row (64 fp32) in registers as 32 packed pairs. K tile (64 keys x 512 fp32)
// in dynamic smem; all lanes of a warp read the same K address (broadcast).
// argmax of Q.K over adj-valid k == reference's winner-take-all index.
// ============================================================================
#define QT 32
#define KT 64
#define SADJ_STRIDE 65
#define SMEM_SCORE (KT * 512 * 4 + QT * SADJ_STRIDE * 4)

__global__ __launch_bounds__(256, 1) void score_argmax(const int* __restrict__ adj)
{
    extern __shared__ float smem[];
    float* sK   = smem;                               // [KT][512]
    int*   sAdj = (int*)(smem + KT * 512);            // [QT][SADJ_STRIDE]

    const int tid  = threadIdx.x;
    const int h    = tid >> 5;        // warp id = head
    const int lane = tid & 31;        // local query
    const int q0   = blockIdx.x * QT;
    const int q    = q0 + lane;

    // Q row -> registers (packed fp32 pairs), 16B loads
    unsigned long long q2[32];
    {
        const ulonglong2* qp =
            (const ulonglong2*)&g_QKV[(size_t)q * E3 + h * HEAD_DIM];
#pragma unroll
        for (int j = 0; j < 16; j++) {
            ulonglong2 v = qp[j];
            q2[2 * j]     = v.x;
            q2[2 * j + 1] = v.y;
        }
    }

    float best  = -1e30f;
    int   bestk = -1;

    for (int k0 = 0; k0 < N_NODES; k0 += KT) {
        __syncthreads();
        // load K tile: KT rows x 512 floats = 8192 float4 / 256 thr = 32 each
#pragma unroll
        for (int it = 0; it < 32; it++) {
            int idx = it * 256 + tid;
            int row = idx >> 7;         // 0..63
            int c4  = idx & 127;
            *(float4*)&sK[row * 512 + c4 * 4] =
                *(const float4*)&g_QKV[(size_t)(k0 + row) * E3 + 512 + c4 * 4];
        }
        // load adj tile: QT x KT ints = 512 int4 / 256 thr = 2 each
#pragma unroll
        for (int it = 0; it < 2; it++) {
            int idx = it * 256 + tid;
            int row = idx >> 4;         // 0..31
            int c4  = idx & 15;
            int4 v = *(const int4*)&adj[(size_t)(q0 + row) * N_NODES + k0 + c4 * 4];
            int* dst = &sAdj[row * SADJ_STRIDE + c4 * 4];
            dst[0] = v.x; dst[1] = v.y; dst[2] = v.z; dst[3] = v.w;
        }
        __syncthreads();

#pragma unroll 2
        for (int kk = 0; kk < KT; kk++) {
            const ulonglong2* kp =
                (const ulonglong2*)&sK[kk * 512 + h * HEAD_DIM];
            unsigned long long a0 = 0ULL, a1 = 0ULL, a2 = 0ULL, a3 = 0ULL;
#pragma unroll
            for (int j = 0; j < 16; j += 2) {
                ulonglong2 v0 = kp[j];
                ulonglong2 v1 = kp[j + 1];
                a0 = fma2(q2[2 * j],     v0.x, a0);
                a1 = fma2(q2[2 * j + 1], v0.y, a1);
                a2 = fma2(q2[2 * j + 2], v1.x, a2);
                a3 = fma2(q2[2 * j + 3], v1.y, a3);
            }
            a0 = add2(a0, a1);
            a2 = add2(a2, a3);
            a0 = add2(a0, a2);
            float lo, hi;
            unpack2(a0, lo, hi);
            float s = lo + hi;
            int m = sAdj[lane * SADJ_STRIDE + kk];
            if (m > 0 && s > best) { best = s; bestk = k0 + kk; }
        }
    }

    g_argmax[h * N_NODES + q] = bestk;
}

// ============================================================================
// Kernel 3: out[q, h*64+d] = V[argmax(h,q), h*64+d] / HEADS   (float4 gather)
// ============================================================================
__global__ __launch_bounds__(256) void gather_out(float* __restrict__ out)
{
    int idx = blockIdx.x * blockDim.x + threadIdx.x;  // one float4 each
    int q   = idx >> 7;           // 128 float4 per output row
    int c4  = idx & 127;
    int h   = c4 >> 4;            // 16 float4 per head
    int k   = g_argmax[h * N_NODES + q];
    float4 v = make_float4(0.f, 0.f, 0.f, 0.f);
    if (k >= 0) {
        float4 t = *(const float4*)&g_QKV[(size_t)k * E3 + 1024 + c4 * 4];
        v.x = t.x * 0.125f;
        v.y = t.y * 0.125f;
        v.z = t.z * 0.125f;
        v.w = t.w * 0.125f;
    }
    *(float4*)&out[(size_t)idx * 4] = v;
}

// ============================================================================
extern "C" void kernel_launch(void* const* d_in, const int* in_sizes, int n_in,
                              void* d_out, int out_size)
{
    const float* x   = (const float*)d_in[0];
    const int*   adj = (const int*)d_in[1];
    const float* WQ  = (const float*)d_in[2];
    const float* WK  = (const float*)d_in[3];
    const float* WV  = (const float*)d_in[4];
    // d_in[5] (we) and d_in[6] (be) are argmax-invariant -> unused.
    float* out = (float*)d_out;

    cudaFuncSetAttribute(score_argmax,
                         cudaFuncAttributeMaxDynamicSharedMemorySize, SMEM_SCORE);

    dim3 g1(1536 / 64, 4096 / 128);            // 24 x 32
    qkv_gemm<<<g1, 256>>>(x, WQ, WK, WV);

    score_argmax<<<N_NODES / QT, 256, SMEM_SCORE>>>(adj);

    gather_out<<<(N_NODES * EMBED / 4) / 256, 256>>>(out);
}

// round 2
// speedup vs baseline: 1.1322x; 1.1322x over previous
#include <cuda_runtime.h>
#include <cstdint>

#define N_NODES 4096
#define IN_FEAT 512
#define E3      1536
#define HEADS   8
#define HEAD_DIM 64

// ---------------- scratch (static device globals: no allocation) ------------
__device__ float    g_xT[IN_FEAT * N_NODES];   // [k][m]
__device__ float    g_WT[IN_FEAT * E3];        // [k][n]  n: 0..511 Q, 512..1023 K, 1024..1535 V
__device__ float    g_Q[N_NODES * 512];
__device__ float    g_K[N_NODES * 512];        // contiguous rows -> single bulk copy per tile
__device__ float    g_V[N_NODES * 512];
__device__ unsigned g_adjbits[128 * N_NODES];  // [word][q]; bit b of word w = adj[q][w*32+b]>0
__device__ int      g_argmax[HEADS * N_NODES];

// ---------------- packed fp32x2 helpers -------------------------------------
__device__ __forceinline__ unsigned long long pack2(float lo, float hi) {
    unsigned long long r;
    asm("mov.b64 %0, {%1, %2};" : "=l"(r) : "f"(lo), "f"(hi));
    return r;
}
__device__ __forceinline__ void unpack2(unsigned long long v, float& lo, float& hi) {
    asm("mov.b64 {%0, %1}, %2;" : "=f"(lo), "=f"(hi) : "l"(v));
}
__device__ __forceinline__ unsigned long long fma2(unsigned long long a,
                                                   unsigned long long b,
                                                   unsigned long long c) {
    unsigned long long d;
    asm("fma.rn.f32x2 %0, %1, %2, %3;" : "=l"(d) : "l"(a), "l"(b), "l"(c));
    return d;
}
__device__ __forceinline__ unsigned long long add2(unsigned long long a,
                                                   unsigned long long b) {
    unsigned long long d;
    asm("add.rn.f32x2 %0, %1, %2;" : "=l"(d) : "l"(a), "l"(b));
    return d;
}

// ---------------- mbarrier + bulk-copy helpers ------------------------------
__device__ __forceinline__ uint32_t smem_u32(const void* p) {
    uint32_t a;
    asm("{ .reg .u64 t; cvta.to.shared.u64 t, %1; cvt.u32.u64 %0, t; }"
        : "=r"(a) : "l"(p));
    return a;
}
__device__ __forceinline__ void mbar_init(uint32_t bar, uint32_t cnt) {
    asm volatile("mbarrier.init.shared.b64 [%0], %1;" :: "r"(bar), "r"(cnt) : "memory");
}
__device__ __forceinline__ void mbar_arrive_expect(uint32_t bar, uint32_t bytes) {
    asm volatile("mbarrier.arrive.expect_tx.shared.b64 _, [%0], %1;"
                 :: "r"(bar), "r"(bytes) : "memory");
}
__device__ __forceinline__ void bulk_g2s(uint32_t dst, const void* src,
                                         uint32_t bytes, uint32_t bar) {
    asm volatile(
        "cp.async.bulk.shared::cluster.global.mbarrier::complete_tx::bytes "
        "[%0], [%1], %2, [%3];"
        :: "r"(dst), "l"(src), "r"(bytes), "r"(bar) : "memory");
}
__device__ __forceinline__ void mbar_wait(uint32_t bar, uint32_t parity) {
    asm volatile(
        "{\n\t"
        ".reg .pred P;\n\t"
        "WL_%=:\n\t"
        "mbarrier.try_wait.parity.acquire.cta.shared::cta.b64 P, [%0], %1, 0x989680;\n\t"
        "@P bra WD_%=;\n\t"
        "bra WL_%=;\n\t"
        "WD_%=:\n\t"
        "}"
        :: "r"(bar), "r"(parity) : "memory");
}

// ============================================================================
// Transposes: x[4096,512] -> xT[512,4096];  W{Q,K,V}[512,512] -> WT[512,1536]
// ============================================================================
__global__ __launch_bounds__(256) void transpose_x(const float* __restrict__ x) {
    __shared__ float t[32][33];
    const int bx = blockIdx.x * 32;   // k
    const int by = blockIdx.y * 32;   // m
    const int txx = threadIdx.x, tyy = threadIdx.y;
#pragma unroll
    for (int i = tyy; i < 32; i += 8)
        t[i][txx] = x[(size_t)(by + i) * IN_FEAT + bx + txx];
    __syncthreads();
#pragma unroll
    for (int i = tyy; i < 32; i += 8)
        g_xT[(size_t)(bx + i) * N_NODES + by + txx] = t[txx][i];
}

__global__ __launch_bounds__(256) void transpose_w(const float* __restrict__ WQ,
                                                   const float* __restrict__ WK,
                                                   const float* __restrict__ WV) {
    const float* W = (blockIdx.z == 0) ? WQ : ((blockIdx.z == 1) ? WK : WV);
    __shared__ float t[32][33];
    const int bx = blockIdx.x * 32;   // k
    const int by = blockIdx.y * 32;   // row of W (output n within 512)
    const int txx = threadIdx.x, tyy = threadIdx.y;
#pragma unroll
    for (int i = tyy; i < 32; i += 8)
        t[i][txx] = W[(size_t)(by + i) * IN_FEAT + bx + txx];
    __syncthreads();
#pragma unroll
    for (int i = tyy; i < 32; i += 8)
        g_WT[(size_t)(bx + i) * E3 + blockIdx.z * 512 + by + txx] = t[txx][i];
}

// ============================================================================
// adj -> bitmask.  warp per query row; word w bit b = adj[q][w*32+b] > 0
// ============================================================================
__global__ __launch_bounds__(256) void adj_to_bits(const int* __restrict__ adj) {
    const int q    = blockIdx.x * 8 + (threadIdx.x >> 5);
    const int lane = threadIdx.x & 31;
    const int* row = adj + (size_t)q * N_NODES;
#pragma unroll 4
    for (int w = 0; w < 128; w++) {
        unsigned m = __ballot_sync(0xffffffffu, row[w * 32 + lane] > 0);
        if (lane == 0) g_adjbits[w * N_NODES + q] = m;
    }
}

// ============================================================================
// QKV GEMM: C[4096,1536] = xT^T @ WT  (i.e. x @ Wcat^T), 128x128 block tile,
// k-tile 64, double-buffered bulk copies, 512 threads, 8m x 4n micro (m-pairs).
// ============================================================================
#define QKV_KT 64
#define QKV_TILE_BYTES (QKV_KT * 128 * 4)           // 32 KB per operand buffer
#define QKV_SMEM (4 * QKV_TILE_BYTES)               // A x2 + B x2 = 128 KB

__device__ __forceinline__ void qkv_issue(int t, int m0, int n0, int tid,
                                          float* As, float* Bs,
                                          uint32_t bar0, uint32_t bar1) {
    if (tid < 128) {
        const int buf = t & 1;
        const uint32_t bar = buf ? bar1 : bar0;
        mbar_arrive_expect(bar, 512);                  // 128 threads x 512 B
        const int row = tid & 63;
        const int k   = t * QKV_KT + row;
        if (tid < 64) {
            bulk_g2s(smem_u32(&As[buf * QKV_KT * 128 + row * 128]),
                     &g_xT[(size_t)k * N_NODES + m0], 512, bar);
        } else {
            bulk_g2s(smem_u32(&Bs[buf * QKV_KT * 128 + row * 128]),
                     &g_WT[(size_t)k * E3 + n0], 512, bar);
        }
    }
}

__global__ __launch_bounds__(512, 1) void qkv_gemm() {
    extern __shared__ float smem[];
    float* As = smem;                         // [2][64][128]
    float* Bs = smem + 2 * QKV_KT * 128;      // [2][64][128]
    __shared__ __align__(8) unsigned long long mbar[2];

    const int tid = threadIdx.x;
    const int tx  = tid & 31;       // n: 32 * 4 = 128
    const int ty  = tid >> 5;       // m: 16 * 8 = 128
    const int n0  = blockIdx.x * 128;
    const int m0  = blockIdx.y * 128;
    const uint32_t bar0 = smem_u32(&mbar[0]);
    const uint32_t bar1 = smem_u32(&mbar[1]);

    if (tid == 0) { mbar_init(bar0, 128); mbar_init(bar1, 128); }
    __syncthreads();

    qkv_issue(0, m0, n0, tid, As, Bs, bar0, bar1);
    qkv_issue(1, m0, n0, tid, As, Bs, bar0, bar1);

    unsigned long long c[4][4];
#pragma unroll
    for (int i = 0; i < 4; i++)
#pragma unroll
        for (int j = 0; j < 4; j++) c[i][j] = 0ULL;

    const int ntiles = IN_FEAT / QKV_KT;      // 8
    for (int t = 0; t < ntiles; t++) {
        const int buf = t & 1;
        mbar_wait(buf ? bar1 : bar0, (t >> 1) & 1);
        const float* a = As + buf * QKV_KT * 128;
        const float* b = Bs + buf * QKV_KT * 128;
#pragma unroll 8
        for (int k = 0; k < QKV_KT; k++) {
            const ulonglong2* ap = (const ulonglong2*)&a[k * 128 + ty * 8];
            ulonglong2 a01 = ap[0];           // pairs (m0,m1),(m2,m3)
            ulonglong2 a23 = ap[1];           // pairs (m4,m5),(m6,m7)
            float4 bv = *(const float4*)&b[k * 128 + tx * 4];
            unsigned long long bd[4];
            bd[0] = pack2(bv.x, bv.x);
            bd[1] = pack2(bv.y, bv.y);
            bd[2] = pack2(bv.z, bv.z);
            bd[3] = pack2(bv.w, bv.w);
#pragma unroll
            for (int j = 0; j < 4; j++) {
                c[0][j] = fma2(a01.x, bd[j], c[0][j]);
                c[1][j] = fma2(a01.y, bd[j], c[1][j]);
                c[2][j] = fma2(a23.x, bd[j], c[2][j]);
                c[3][j] = fma2(a23.y, bd[j], c[3][j]);
            }
        }
        __syncthreads();
        if (t + 2 < ntiles) qkv_issue(t + 2, m0, n0, tid, As, Bs, bar0, bar1);
    }

    float* outp = (n0 < 512) ? g_Q : ((n0 < 1024) ? g_K : g_V);
    const int nn = n0 & 511;
#pragma unroll
    for (int mp = 0; mp < 4; mp++) {
        float lo0, hi0, lo1, hi1, lo2, hi2, lo3, hi3;
        unpack2(c[mp][0], lo0, hi0);
        unpack2(c[mp][1], lo1, hi1);
        unpack2(c[mp][2], lo2, hi2);
        unpack2(c[mp][3], lo3, hi3);
        const int row0 = m0 + ty * 8 + mp * 2;
        *(float4*)&outp[(size_t)row0 * 512 + nn + tx * 4] =
            make_float4(lo0, lo1, lo2, lo3);
        *(float4*)&outp[(size_t)(row0 + 1) * 512 + nn + tx * 4] =
            make_float4(hi0, hi1, hi2, hi3);
    }
}

// ============================================================================
// Masked score argmax.  Block = 32 queries x 8 heads (warp=head, lane=query).
// K tiles (32 keys x 512 f32 = 64 KB) double-buffered via single bulk copies.
// adj replaced by 32-bit mask word per (tile, query), prefetched one tile ahead.
// ============================================================================
#define KT 32
#define SC_TILE_BYTES (KT * 512 * 4)          // 64 KB
#define SC_SMEM (2 * SC_TILE_BYTES)           // 128 KB

__device__ __forceinline__ void sc_issue(int t, int tid, float* sK,
                                         uint32_t bar0, uint32_t bar1) {
    if (tid == 0) {
        const int buf = t & 1;
        const uint32_t bar = buf ? bar1 : bar0;
        mbar_arrive_expect(bar, SC_TILE_BYTES);
        bulk_g2s(smem_u32(&sK[buf * KT * 512]),
                 &g_K[(size_t)t * KT * 512], SC_TILE_BYTES, bar);
    }
}

__global__ __launch_bounds__(256, 1) void score_argmax() {
    extern __shared__ float sK[];             // [2][KT][512]
    __shared__ __align__(8) unsigned long long mbar[2];

    const int tid  = threadIdx.x;
    const int h    = tid >> 5;
    const int lane = tid & 31;
    const int q    = blockIdx.x * 32 + lane;
    const uint32_t bar0 = smem_u32(&mbar[0]);
    const uint32_t bar1 = smem_u32(&mbar[1]);

    if (tid == 0) { mbar_init(bar0, 1); mbar_init(bar1, 1); }
    __syncthreads();

    sc_issue(0, tid, sK, bar0, bar1);
    sc_issue(1, tid, sK, bar0, bar1);

    // Q row -> registers as packed fp32 pairs
    unsigned long long q2[32];
    {
        const ulonglong2* qp = (const ulonglong2*)&g_Q[(size_t)q * 512 + h * HEAD_DIM];
#pragma unroll
        for (int j = 0; j < 16; j++) {
            ulonglong2 v = qp[j];
            q2[2 * j]     = v.x;
            q2[2 * j + 1] = v.y;
        }
    }

    float best  = -1e30f;
    int   bestk = -1;
    const int ntiles = N_NODES / KT;          // 128
    unsigned nextmask = g_adjbits[q];         // tile 0 word

    for (int t = 0; t < ntiles; t++) {
        const unsigned mask = nextmask;
        if (t + 1 < ntiles) nextmask = g_adjbits[(t + 1) * N_NODES + q];
        const int buf = t & 1;
        mbar_wait(buf ? bar1 : bar0, (t >> 1) & 1);
        const float* kb = sK + buf * KT * 512 + h * HEAD_DIM;

#pragma unroll 2
        for (int kk = 0; kk < KT; kk++) {
            const ulonglong2* kp = (const ulonglong2*)(kb + kk * 512);
            unsigned long long a0 = 0ULL, a1 = 0ULL, a2 = 0ULL, a3 = 0ULL;
#pragma unroll
            for (int j = 0; j < 16; j += 2) {
                ulonglong2 v0 = kp[j];
                ulonglong2 v1 = kp[j + 1];
                a0 = fma2(q2[2 * j],     v0.x, a0);
                a1 = fma2(q2[2 * j + 1], v0.y, a1);
                a2 = fma2(q2[2 * j + 2], v1.x, a2);
                a3 = fma2(q2[2 * j + 3], v1.y, a3);
            }
            a0 = add2(a0, a1);
            a2 = add2(a2, a3);
            a0 = add2(a0, a2);
            float lo, hi;
            unpack2(a0, lo, hi);
            const float s = lo + hi;
            if (((mask >> kk) & 1u) && s > best) { best = s; bestk = t * KT + kk; }
        }
        __syncthreads();
        if (t + 2 < ntiles) sc_issue(t + 2, tid, sK, bar0, bar1);
    }

    g_argmax[h * N_NODES + q] = bestk;
}

// ============================================================================
// out[q, h*64+d] = V[argmax(h,q), h*64+d] / HEADS
// ============================================================================
__global__ __launch_bounds__(256) void gather_out(float* __restrict__ out) {
    const int idx = blockIdx.x * blockDim.x + threadIdx.x;  // one float4 each
    const int q   = idx >> 7;
    const int c4  = idx & 127;
    const int h   = c4 >> 4;
    const int k   = g_argmax[h * N_NODES + q];
    float4 v = make_float4(0.f, 0.f, 0.f, 0.f);
    if (k >= 0) {
        float4 t = *(const float4*)&g_V[(size_t)k * 512 + c4 * 4];
        v.x = t.x * 0.125f;
        v.y = t.y * 0.125f;
        v.z = t.z * 0.125f;
        v.w = t.w * 0.125f;
    }
    *(float4*)&out[(size_t)idx * 4] = v;
}

// ============================================================================
extern "C" void kernel_launch(void* const* d_in, const int* in_sizes, int n_in,
                              void* d_out, int out_size)
{
    const float* x   = (const float*)d_in[0];
    const int*   adj = (const int*)d_in[1];
    const float* WQ  = (const float*)d_in[2];
    const float* WK  = (const float*)d_in[3];
    const float* WV  = (const float*)d_in[4];
    // we/be are argmax-invariant -> unused
    float* out = (float*)d_out;

    cudaFuncSetAttribute(qkv_gemm,
                         cudaFuncAttributeMaxDynamicSharedMemorySize, QKV_SMEM);
    cudaFuncSetAttribute(score_argmax,
                         cudaFuncAttributeMaxDynamicSharedMemorySize, SC_SMEM);

    dim3 tb(32, 8);
    transpose_x<<<dim3(IN_FEAT / 32, N_NODES / 32), tb>>>(x);
    transpose_w<<<dim3(IN_FEAT / 32, 512 / 32, 3), tb>>>(WQ, WK, WV);
    adj_to_bits<<<N_NODES / 8, 256>>>(adj);

    qkv_gemm<<<dim3(E3 / 128, N_NODES / 128), 512, QKV_SMEM>>>();

    score_argmax<<<N_NODES / 32, 256, SC_SMEM>>>();

    gather_out<<<(N_NODES * 512 / 4) / 256, 256>>>(out);
}

// round 3
// speedup vs baseline: 1.1698x; 1.0332x over previous
#include <cuda_runtime.h>
#include <cstdint>

#define N_NODES 4096
#define IN_FEAT 512
#define E3      1536
#define HEADS   8
#define HEAD_DIM 64

// ---------------- scratch (static device globals: no allocation) ------------
__device__ float    g_xT[IN_FEAT * N_NODES];   // [k][m]
__device__ float    g_WT[IN_FEAT * E3];        // [k][n]
__device__ float    g_Q[N_NODES * 512];
__device__ float    g_K[N_NODES * 512];
__device__ float    g_V[N_NODES * 512];
__device__ unsigned g_adjbits[128 * N_NODES];  // [word][q]
__device__ float    g_pbest[2][HEADS * N_NODES];
__device__ int      g_pidx [2][HEADS * N_NODES];

// ---------------- packed fp32x2 helpers -------------------------------------
__device__ __forceinline__ unsigned long long pack2(float lo, float hi) {
    unsigned long long r;
    asm("mov.b64 %0, {%1, %2};" : "=l"(r) : "f"(lo), "f"(hi));
    return r;
}
__device__ __forceinline__ void unpack2(unsigned long long v, float& lo, float& hi) {
    asm("mov.b64 {%0, %1}, %2;" : "=f"(lo), "=f"(hi) : "l"(v));
}
__device__ __forceinline__ unsigned long long fma2(unsigned long long a,
                                                   unsigned long long b,
                                                   unsigned long long c) {
    unsigned long long d;
    asm("fma.rn.f32x2 %0, %1, %2, %3;" : "=l"(d) : "l"(a), "l"(b), "l"(c));
    return d;
}
__device__ __forceinline__ unsigned long long add2(unsigned long long a,
                                                   unsigned long long b) {
    unsigned long long d;
    asm("add.rn.f32x2 %0, %1, %2;" : "=l"(d) : "l"(a), "l"(b));
    return d;
}

// ---------------- mbarrier + bulk-copy helpers ------------------------------
__device__ __forceinline__ uint32_t smem_u32(const void* p) {
    uint32_t a;
    asm("{ .reg .u64 t; cvta.to.shared.u64 t, %1; cvt.u32.u64 %0, t; }"
        : "=r"(a) : "l"(p));
    return a;
}
__device__ __forceinline__ void mbar_init(uint32_t bar, uint32_t cnt) {
    asm volatile("mbarrier.init.shared.b64 [%0], %1;" :: "r"(bar), "r"(cnt) : "memory");
}
__device__ __forceinline__ void mbar_arrive_expect(uint32_t bar, uint32_t bytes) {
    asm volatile("mbarrier.arrive.expect_tx.shared.b64 _, [%0], %1;"
                 :: "r"(bar), "r"(bytes) : "memory");
}
__device__ __forceinline__ void bulk_g2s(uint32_t dst, const void* src,
                                         uint32_t bytes, uint32_t bar) {
    asm volatile(
        "cp.async.bulk.shared::cluster.global.mbarrier::complete_tx::bytes "
        "[%0], [%1], %2, [%3];"
        :: "r"(dst), "l"(src), "r"(bytes), "r"(bar) : "memory");
}
__device__ __forceinline__ void mbar_wait(uint32_t bar, uint32_t parity) {
    asm volatile(
        "{\n\t"
        ".reg .pred P;\n\t"
        "WL_%=:\n\t"
        "mbarrier.try_wait.parity.acquire.cta.shared::cta.b64 P, [%0], %1, 0x989680;\n\t"
        "@P bra WD_%=;\n\t"
        "bra WL_%=;\n\t"
        "WD_%=:\n\t"
        "}"
        :: "r"(bar), "r"(parity) : "memory");
}

// ============================================================================
// Transposes
// ============================================================================
__global__ __launch_bounds__(256) void transpose_x(const float* __restrict__ x) {
    __shared__ float t[32][33];
    const int bx = blockIdx.x * 32;   // k
    const int by = blockIdx.y * 32;   // m
    const int txx = threadIdx.x, tyy = threadIdx.y;
#pragma unroll
    for (int i = tyy; i < 32; i += 8)
        t[i][txx] = x[(size_t)(by + i) * IN_FEAT + bx + txx];
    __syncthreads();
#pragma unroll
    for (int i = tyy; i < 32; i += 8)
        g_xT[(size_t)(bx + i) * N_NODES + by + txx] = t[txx][i];
}

__global__ __launch_bounds__(256) void transpose_w(const float* __restrict__ WQ,
                                                   const float* __restrict__ WK,
                                                   const float* __restrict__ WV) {
    const float* W = (blockIdx.z == 0) ? WQ : ((blockIdx.z == 1) ? WK : WV);
    __shared__ float t[32][33];
    const int bx = blockIdx.x * 32;   // k
    const int by = blockIdx.y * 32;   // n within 512
    const int txx = threadIdx.x, tyy = threadIdx.y;
#pragma unroll
    for (int i = tyy; i < 32; i += 8)
        t[i][txx] = W[(size_t)(by + i) * IN_FEAT + bx + txx];
    __syncthreads();
#pragma unroll
    for (int i = tyy; i < 32; i += 8)
        g_WT[(size_t)(bx + i) * E3 + blockIdx.z * 512 + by + txx] = t[txx][i];
}

// ============================================================================
// adj -> bitmask
// ============================================================================
__global__ __launch_bounds__(256) void adj_to_bits(const int* __restrict__ adj) {
    const int q    = blockIdx.x * 8 + (threadIdx.x >> 5);
    const int lane = threadIdx.x & 31;
    const int* row = adj + (size_t)q * N_NODES;
#pragma unroll 4
    for (int w = 0; w < 128; w++) {
        unsigned m = __ballot_sync(0xffffffffu, row[w * 32 + lane] > 0);
        if (lane == 0) g_adjbits[w * N_NODES + q] = m;
    }
}

// ============================================================================
// QKV GEMM (unchanged from R2): 128x128 tile, k-tile 64, double-buffered bulk.
// ============================================================================
#define QKV_KT 64
#define QKV_TILE_BYTES (QKV_KT * 128 * 4)
#define QKV_SMEM (4 * QKV_TILE_BYTES)

__device__ __forceinline__ void qkv_issue(int t, int m0, int n0, int tid,
                                          float* As, float* Bs,
                                          uint32_t bar0, uint32_t bar1) {
    if (tid < 128) {
        const int buf = t & 1;
        const uint32_t bar = buf ? bar1 : bar0;
        mbar_arrive_expect(bar, 512);
        const int row = tid & 63;
        const int k   = t * QKV_KT + row;
        if (tid < 64) {
            bulk_g2s(smem_u32(&As[buf * QKV_KT * 128 + row * 128]),
                     &g_xT[(size_t)k * N_NODES + m0], 512, bar);
        } else {
            bulk_g2s(smem_u32(&Bs[buf * QKV_KT * 128 + row * 128]),
                     &g_WT[(size_t)k * E3 + n0], 512, bar);
        }
    }
}

__global__ __launch_bounds__(512, 1) void qkv_gemm() {
    extern __shared__ float smem[];
    float* As = smem;
    float* Bs = smem + 2 * QKV_KT * 128;
    __shared__ __align__(8) unsigned long long mbar[2];

    const int tid = threadIdx.x;
    const int tx  = tid & 31;
    const int ty  = tid >> 5;
    const int n0  = blockIdx.x * 128;
    const int m0  = blockIdx.y * 128;
    const uint32_t bar0 = smem_u32(&mbar[0]);
    const uint32_t bar1 = smem_u32(&mbar[1]);

    if (tid == 0) { mbar_init(bar0, 128); mbar_init(bar1, 128); }
    __syncthreads();

    qkv_issue(0, m0, n0, tid, As, Bs, bar0, bar1);
    qkv_issue(1, m0, n0, tid, As, Bs, bar0, bar1);

    unsigned long long c[4][4];
#pragma unroll
    for (int i = 0; i < 4; i++)
#pragma unroll
        for (int j = 0; j < 4; j++) c[i][j] = 0ULL;

    const int ntiles = IN_FEAT / QKV_KT;
    for (int t = 0; t < ntiles; t++) {
        const int buf = t & 1;
        mbar_wait(buf ? bar1 : bar0, (t >> 1) & 1);
        const float* a = As + buf * QKV_KT * 128;
        const float* b = Bs + buf * QKV_KT * 128;
#pragma unroll 8
        for (int k = 0; k < QKV_KT; k++) {
            const ulonglong2* ap = (const ulonglong2*)&a[k * 128 + ty * 8];
            ulonglong2 a01 = ap[0];
            ulonglong2 a23 = ap[1];
            float4 bv = *(const float4*)&b[k * 128 + tx * 4];
            unsigned long long bd[4];
            bd[0] = pack2(bv.x, bv.x);
            bd[1] = pack2(bv.y, bv.y);
            bd[2] = pack2(bv.z, bv.z);
            bd[3] = pack2(bv.w, bv.w);
#pragma unroll
            for (int j = 0; j < 4; j++) {
                c[0][j] = fma2(a01.x, bd[j], c[0][j]);
                c[1][j] = fma2(a01.y, bd[j], c[1][j]);
                c[2][j] = fma2(a23.x, bd[j], c[2][j]);
                c[3][j] = fma2(a23.y, bd[j], c[3][j]);
            }
        }
        __syncthreads();
        if (t + 2 < ntiles) qkv_issue(t + 2, m0, n0, tid, As, Bs, bar0, bar1);
    }

    float* outp = (n0 < 512) ? g_Q : ((n0 < 1024) ? g_K : g_V);
    const int nn = n0 & 511;
#pragma unroll
    for (int mp = 0; mp < 4; mp++) {
        float lo0, hi0, lo1, hi1, lo2, hi2, lo3, hi3;
        unpack2(c[mp][0], lo0, hi0);
        unpack2(c[mp][1], lo1, hi1);
        unpack2(c[mp][2], lo2, hi2);
        unpack2(c[mp][3], lo3, hi3);
        const int row0 = m0 + ty * 8 + mp * 2;
        *(float4*)&outp[(size_t)row0 * 512 + nn + tx * 4] =
            make_float4(lo0, lo1, lo2, lo3);
        *(float4*)&outp[(size_t)(row0 + 1) * 512 + nn + tx * 4] =
            make_float4(hi0, hi1, hi2, hi3);
    }
}

// ============================================================================
// Masked score argmax, K-SPLIT x2 for occupancy.
// Block = 32 queries x 8 heads; blockIdx.y = which half of the 4096 keys.
// KT=16 keys/tile (32 KB), double-buffered -> 64 KB smem -> 2 blocks/SM
// -> 4 warps/SMSP. 256 blocks fill 128 SMs in one wave.
// ============================================================================
#define KT 16
#define K_HALF 2048
#define SC_TILE_BYTES (KT * 512 * 4)          // 32 KB
#define SC_SMEM (2 * SC_TILE_BYTES)           // 64 KB

__device__ __forceinline__ void sc_issue(int t, int kbase, int tid, float* sK,
                                         uint32_t bar0, uint32_t bar1) {
    if (tid == 0) {
        const int buf = t & 1;
        const uint32_t bar = buf ? bar1 : bar0;
        mbar_arrive_expect(bar, SC_TILE_BYTES);
        bulk_g2s(smem_u32(&sK[buf * KT * 512]),
                 &g_K[(size_t)(kbase + t * KT) * 512], SC_TILE_BYTES, bar);
    }
}

__global__ __launch_bounds__(256, 2) void score_argmax() {
    extern __shared__ float sK[];             // [2][KT][512]
    __shared__ __align__(8) unsigned long long mbar[2];

    const int tid   = threadIdx.x;
    const int h     = tid >> 5;
    const int lane  = tid & 31;
    const int q     = blockIdx.x * 32 + lane;
    const int half  = blockIdx.y;
    const int kbase = half * K_HALF;
    const uint32_t bar0 = smem_u32(&mbar[0]);
    const uint32_t bar1 = smem_u32(&mbar[1]);

    if (tid == 0) { mbar_init(bar0, 1); mbar_init(bar1, 1); }
    __syncthreads();

    sc_issue(0, kbase, tid, sK, bar0, bar1);
    sc_issue(1, kbase, tid, sK, bar0, bar1);

    // Q row -> registers as packed fp32 pairs
    unsigned long long q2[32];
    {
        const ulonglong2* qp = (const ulonglong2*)&g_Q[(size_t)q * 512 + h * HEAD_DIM];
#pragma unroll
        for (int j = 0; j < 16; j++) {
            ulonglong2 v = qp[j];
            q2[2 * j]     = v.x;
            q2[2 * j + 1] = v.y;
        }
    }

    float best  = -1e30f;
    int   bestk = -1;
    const int ntiles = K_HALF / KT;           // 128
    // mask word covers 32 keys = 2 tiles; prefetch one word ahead
    unsigned nextword = g_adjbits[(kbase >> 5) * N_NODES + q];

    for (int t = 0; t < ntiles; t++) {
        const int k0 = kbase + t * KT;
        unsigned word = nextword;
        if ((t & 1) && (t + 1 < ntiles))
            nextword = g_adjbits[(((k0 + KT) >> 5)) * N_NODES + q];
        const unsigned mask = (k0 & 16) ? (word >> 16) : (word & 0xffffu);

        const int buf = t & 1;
        mbar_wait(buf ? bar1 : bar0, (t >> 1) & 1);
        const float* kb = sK + buf * KT * 512 + h * HEAD_DIM;

#pragma unroll 2
        for (int kk = 0; kk < KT; kk++) {
            const ulonglong2* kp = (const ulonglong2*)(kb + kk * 512);
            unsigned long long a0 = 0ULL, a1 = 0ULL, a2 = 0ULL, a3 = 0ULL;
#pragma unroll
            for (int j = 0; j < 16; j += 2) {
                ulonglong2 v0 = kp[j];
                ulonglong2 v1 = kp[j + 1];
                a0 = fma2(q2[2 * j],     v0.x, a0);
                a1 = fma2(q2[2 * j + 1], v0.y, a1);
                a2 = fma2(q2[2 * j + 2], v1.x, a2);
                a3 = fma2(q2[2 * j + 3], v1.y, a3);
            }
            a0 = add2(a0, a1);
            a2 = add2(a2, a3);
            a0 = add2(a0, a2);
            float lo, hi;
            unpack2(a0, lo, hi);
            const float s = lo + hi;
            if (((mask >> kk) & 1u) && s > best) { best = s; bestk = k0 + kk; }
        }
        __syncthreads();
        if (t + 2 < ntiles) sc_issue(t + 2, kbase, tid, sK, bar0, bar1);
    }

    g_pbest[half][h * N_NODES + q] = best;
    g_pidx [half][h * N_NODES + q] = bestk;
}

// ============================================================================
// gather + 2-way argmax reduce:
// out[q, h*64+d] = V[argmax over halves, h*64+d] / HEADS
// ============================================================================
__global__ __launch_bounds__(256) void gather_out(float* __restrict__ out) {
    const int idx = blockIdx.x * blockDim.x + threadIdx.x;  // one float4 each
    const int q   = idx >> 7;
    const int c4  = idx & 127;
    const int h   = c4 >> 4;
    const int hq  = h * N_NODES + q;
    const float b0 = g_pbest[0][hq];
    const float b1 = g_pbest[1][hq];
    const int   k  = (b1 > b0) ? g_pidx[1][hq] : g_pidx[0][hq];
    float4 v = make_float4(0.f, 0.f, 0.f, 0.f);
    if (k >= 0) {
        float4 t = *(const float4*)&g_V[(size_t)k * 512 + c4 * 4];
        v.x = t.x * 0.125f;
        v.y = t.y * 0.125f;
        v.z = t.z * 0.125f;
        v.w = t.w * 0.125f;
    }
    *(float4*)&out[(size_t)idx * 4] = v;
}

// ============================================================================
extern "C" void kernel_launch(void* const* d_in, const int* in_sizes, int n_in,
                              void* d_out, int out_size)
{
    const float* x   = (const float*)d_in[0];
    const int*   adj = (const int*)d_in[1];
    const float* WQ  = (const float*)d_in[2];
    const float* WK  = (const float*)d_in[3];
    const float* WV  = (const float*)d_in[4];
    float* out = (float*)d_out;

    cudaFuncSetAttribute(qkv_gemm,
                         cudaFuncAttributeMaxDynamicSharedMemorySize, QKV_SMEM);
    cudaFuncSetAttribute(score_argmax,
                         cudaFuncAttributeMaxDynamicSharedMemorySize, SC_SMEM);

    dim3 tb(32, 8);
    transpose_x<<<dim3(IN_FEAT / 32, N_NODES / 32), tb>>>(x);
    transpose_w<<<dim3(IN_FEAT / 32, 512 / 32, 3), tb>>>(WQ, WK, WV);
    adj_to_bits<<<N_NODES / 8, 256>>>(adj);

    qkv_gemm<<<dim3(E3 / 128, N_NODES / 128), 512, QKV_SMEM>>>();

    score_argmax<<<dim3(N_NODES / 32, 2), 256, SC_SMEM>>>();

    gather_out<<<(N_NODES * 512 / 4) / 256, 256>>>(out);
}

// round 5
// speedup vs baseline: 1.4149x; 1.2096x over previous
#include <cuda_runtime.h>
#include <cstdint>

#define N_NODES 4096
#define IN_FEAT 512
#define E3      1536
#define HEADS   8
#define HEAD_DIM 64
#define BAND    0.075f

// ---------------- scratch (static device globals: no allocation) ------------
__device__ float    g_xT[IN_FEAT * N_NODES];     // [k][m]
__device__ float    g_WT[IN_FEAT * E3];          // [k][n]
__device__ float    g_Qh[HEADS * N_NODES * 64];  // head-major [h][node][d]
__device__ float    g_Kh[HEADS * N_NODES * 64];
__device__ float    g_V[N_NODES * 512];          // node-major
__device__ unsigned g_adjbits[128 * N_NODES];    // [word][q]
__device__ int      g_argmax[HEADS * N_NODES];
__device__ int      g_fixcount;
__device__ int      g_fixlist[HEADS * N_NODES];

// ---------------- packed fp32x2 helpers (qkv gemm) ---------------------------
__device__ __forceinline__ unsigned long long pack2(float lo, float hi) {
    unsigned long long r;
    asm("mov.b64 %0, {%1, %2};" : "=l"(r) : "f"(lo), "f"(hi));
    return r;
}
__device__ __forceinline__ void unpack2(unsigned long long v, float& lo, float& hi) {
    asm("mov.b64 {%0, %1}, %2;" : "=f"(lo), "=f"(hi) : "l"(v));
}
__device__ __forceinline__ unsigned long long fma2(unsigned long long a,
                                                   unsigned long long b,
                                                   unsigned long long c) {
    unsigned long long d;
    asm("fma.rn.f32x2 %0, %1, %2, %3;" : "=l"(d) : "l"(a), "l"(b), "l"(c));
    return d;
}

// ---------------- mbarrier + bulk-copy helpers (qkv gemm) --------------------
__device__ __forceinline__ uint32_t smem_u32(const void* p) {
    uint32_t a;
    asm("{ .reg .u64 t; cvta.to.shared.u64 t, %1; cvt.u32.u64 %0, t; }"
        : "=r"(a) : "l"(p));
    return a;
}
__device__ __forceinline__ void mbar_init(uint32_t bar, uint32_t cnt) {
    asm volatile("mbarrier.init.shared.b64 [%0], %1;" :: "r"(bar), "r"(cnt) : "memory");
}
__device__ __forceinline__ void mbar_arrive_expect(uint32_t bar, uint32_t bytes) {
    asm volatile("mbarrier.arrive.expect_tx.shared.b64 _, [%0], %1;"
                 :: "r"(bar), "r"(bytes) : "memory");
}
__device__ __forceinline__ void bulk_g2s(uint32_t dst, const void* src,
                                         uint32_t bytes, uint32_t bar) {
    asm volatile(
        "cp.async.bulk.shared::cluster.global.mbarrier::complete_tx::bytes "
        "[%0], [%1], %2, [%3];"
        :: "r"(dst), "l"(src), "r"(bytes), "r"(bar) : "memory");
}
__device__ __forceinline__ void mbar_wait(uint32_t bar, uint32_t parity) {
    asm volatile(
        "{\n\t"
        ".reg .pred P;\n\t"
        "WL_%=:\n\t"
        "mbarrier.try_wait.parity.acquire.cta.shared::cta.b64 P, [%0], %1, 0x989680;\n\t"
        "@P bra WD_%=;\n\t"
        "bra WL_%=;\n\t"
        "WD_%=:\n\t"
        "}"
        :: "r"(bar), "r"(parity) : "memory");
}

// ---------------- tf32 helpers -----------------------------------------------
__device__ __forceinline__ uint32_t tf32u(float x) {
    uint32_t u;
    asm("cvt.rna.tf32.f32 %0, %1;" : "=r"(u) : "f"(x));
    return u;
}
__device__ __forceinline__ float tf32f(float x) {
    return __uint_as_float(tf32u(x));
}
// mma.sync m16n8k8 tf32, fp32 accumulate (sm_80+ PTX; legal on compute_103)
__device__ __forceinline__ void mma8(float* d, const uint32_t* a,
                                     uint32_t b0, uint32_t b1) {
    asm("mma.sync.aligned.m16n8k8.row.col.f32.tf32.tf32.f32 "
        "{%0,%1,%2,%3}, {%4,%5,%6,%7}, {%8,%9}, {%0,%1,%2,%3};"
        : "+f"(d[0]), "+f"(d[1]), "+f"(d[2]), "+f"(d[3])
        : "r"(a[0]), "r"(a[1]), "r"(a[2]), "r"(a[3]), "r"(b0), "r"(b1));
}

// ============================================================================
// Transposes (unchanged)
// ============================================================================
__global__ __launch_bounds__(256) void transpose_x(const float* __restrict__ x) {
    __shared__ float t[32][33];
    const int bx = blockIdx.x * 32, by = blockIdx.y * 32;
    const int txx = threadIdx.x, tyy = threadIdx.y;
#pragma unroll
    for (int i = tyy; i < 32; i += 8)
        t[i][txx] = x[(size_t)(by + i) * IN_FEAT + bx + txx];
    __syncthreads();
#pragma unroll
    for (int i = tyy; i < 32; i += 8)
        g_xT[(size_t)(bx + i) * N_NODES + by + txx] = t[txx][i];
}

__global__ __launch_bounds__(256) void transpose_w(const float* __restrict__ WQ,
                                                   const float* __restrict__ WK,
                                                   const float* __restrict__ WV) {
    const float* W = (blockIdx.z == 0) ? WQ : ((blockIdx.z == 1) ? WK : WV);
    __shared__ float t[32][33];
    const int bx = blockIdx.x * 32, by = blockIdx.y * 32;
    const int txx = threadIdx.x, tyy = threadIdx.y;
#pragma unroll
    for (int i = tyy; i < 32; i += 8)
        t[i][txx] = W[(size_t)(by + i) * IN_FEAT + bx + txx];
    __syncthreads();
#pragma unroll
    for (int i = tyy; i < 32; i += 8)
        g_WT[(size_t)(bx + i) * E3 + blockIdx.z * 512 + by + txx] = t[txx][i];
}

// ============================================================================
// adj -> bitmask  [word][q]
// ============================================================================
__global__ __launch_bounds__(256) void adj_to_bits(const int* __restrict__ adj) {
    const int q    = blockIdx.x * 8 + (threadIdx.x >> 5);
    const int lane = threadIdx.x & 31;
    const int* row = adj + (size_t)q * N_NODES;
#pragma unroll 4
    for (int w = 0; w < 128; w++) {
        unsigned m = __ballot_sync(0xffffffffu, row[w * 32 + lane] > 0);
        if (lane == 0) g_adjbits[w * N_NODES + q] = m;
    }
}

// ============================================================================
// QKV GEMM (fp32-exact, 134us) — output now head-major for Q/K.
// ============================================================================
#define QKV_KT 64
#define QKV_SMEM (4 * QKV_KT * 128 * 4)

__device__ __forceinline__ void qkv_issue(int t, int m0, int n0, int tid,
                                          float* As, float* Bs,
                                          uint32_t bar0, uint32_t bar1) {
    if (tid < 128) {
        const int buf = t & 1;
        const uint32_t bar = buf ? bar1 : bar0;
        mbar_arrive_expect(bar, 512);
        const int row = tid & 63;
        const int k   = t * QKV_KT + row;
        if (tid < 64) {
            bulk_g2s(smem_u32(&As[buf * QKV_KT * 128 + row * 128]),
                     &g_xT[(size_t)k * N_NODES + m0], 512, bar);
        } else {
            bulk_g2s(smem_u32(&Bs[buf * QKV_KT * 128 + row * 128]),
                     &g_WT[(size_t)k * E3 + n0], 512, bar);
        }
    }
}

__global__ __launch_bounds__(512, 1) void qkv_gemm() {
    extern __shared__ float smem[];
    float* As = smem;
    float* Bs = smem + 2 * QKV_KT * 128;
    __shared__ __align__(8) unsigned long long mbar[2];

    const int tid = threadIdx.x;
    const int tx  = tid & 31;
    const int ty  = tid >> 5;
    const int n0  = blockIdx.x * 128;
    const int m0  = blockIdx.y * 128;
    const uint32_t bar0 = smem_u32(&mbar[0]);
    const uint32_t bar1 = smem_u32(&mbar[1]);

    if (blockIdx.x == 0 && blockIdx.y == 0 && tid == 0) g_fixcount = 0;

    if (tid == 0) { mbar_init(bar0, 128); mbar_init(bar1, 128); }
    __syncthreads();

    qkv_issue(0, m0, n0, tid, As, Bs, bar0, bar1);
    qkv_issue(1, m0, n0, tid, As, Bs, bar0, bar1);

    unsigned long long c[4][4];
#pragma unroll
    for (int i = 0; i < 4; i++)
#pragma unroll
        for (int j = 0; j < 4; j++) c[i][j] = 0ULL;

    const int ntiles = IN_FEAT / QKV_KT;
    for (int t = 0; t < ntiles; t++) {
        const int buf = t & 1;
        mbar_wait(buf ? bar1 : bar0, (t >> 1) & 1);
        const float* a = As + buf * QKV_KT * 128;
        const float* b = Bs + buf * QKV_KT * 128;
#pragma unroll 8
        for (int k = 0; k < QKV_KT; k++) {
            const ulonglong2* ap = (const ulonglong2*)&a[k * 128 + ty * 8];
            ulonglong2 a01 = ap[0];
            ulonglong2 a23 = ap[1];
            float4 bv = *(const float4*)&b[k * 128 + tx * 4];
            unsigned long long bd[4];
            bd[0] = pack2(bv.x, bv.x);
            bd[1] = pack2(bv.y, bv.y);
            bd[2] = pack2(bv.z, bv.z);
            bd[3] = pack2(bv.w, bv.w);
#pragma unroll
            for (int j = 0; j < 4; j++) {
                c[0][j] = fma2(a01.x, bd[j], c[0][j]);
                c[1][j] = fma2(a01.y, bd[j], c[1][j]);
                c[2][j] = fma2(a23.x, bd[j], c[2][j]);
                c[3][j] = fma2(a23.y, bd[j], c[3][j]);
            }
        }
        __syncthreads();
        if (t + 2 < ntiles) qkv_issue(t + 2, m0, n0, tid, As, Bs, bar0, bar1);
    }

    // head-major output for Q/K, node-major for V
    const int col = (n0 & 511) + tx * 4;
    float* pb;
    size_t rs;
    if (n0 < 512)       { pb = g_Qh + (size_t)(col >> 6) * (N_NODES * 64) + (col & 63); rs = 64; }
    else if (n0 < 1024) { pb = g_Kh + (size_t)(col >> 6) * (N_NODES * 64) + (col & 63); rs = 64; }
    else                { pb = g_V + col; rs = 512; }

#pragma unroll
    for (int mp = 0; mp < 4; mp++) {
        float lo0, hi0, lo1, hi1, lo2, hi2, lo3, hi3;
        unpack2(c[mp][0], lo0, hi0);
        unpack2(c[mp][1], lo1, hi1);
        unpack2(c[mp][2], lo2, hi2);
        unpack2(c[mp][3], lo3, hi3);
        const size_t row0 = m0 + ty * 8 + mp * 2;
        *(float4*)&pb[row0 * rs]       = make_float4(lo0, lo1, lo2, lo3);
        *(float4*)&pb[(row0 + 1) * rs] = make_float4(hi0, hi1, hi2, hi3);
    }
}

// ============================================================================
// Score argmax via mma.sync tf32 (pass 1) + banded flagging.
// Block = 64 q rows x 1 head; 4 warps (warp w: rows w*16..w*16+15); 512 blocks.
// K tiles 64x64 fp32 in XOR-swizzled smem (16KB); occupancy 4.
// ============================================================================
__global__ __launch_bounds__(128, 4) void score_mma() {
    __shared__ float sK[64 * 64];

    const int tid  = threadIdx.x;
    const int w    = tid >> 5;
    const int lane = tid & 31;
    const int g    = lane >> 2;
    const int l4   = lane & 3;
    const int h    = blockIdx.y;
    const int qt   = blockIdx.x;
    const int qA   = qt * 64 + w * 16 + g;     // rows for c0,c1
    const int qB   = qA + 8;                   // rows for c2,c3

    // A fragments (tf32-rounded Q), register-resident for whole kernel
    uint32_t a[8][4];
    {
        const float* Qp  = g_Qh + ((size_t)h * N_NODES + qA) * 64;
        const float* Qp8 = Qp + 8 * 64;
#pragma unroll
        for (int s = 0; s < 8; s++) {
            a[s][0] = tf32u(Qp [s * 8 + l4]);
            a[s][1] = tf32u(Qp8[s * 8 + l4]);
            a[s][2] = tf32u(Qp [s * 8 + 4 + l4]);
            a[s][3] = tf32u(Qp8[s * 8 + 4 + l4]);
        }
    }

    float bestA = -3e38f, best2A = -3e38f;
    float bestB = -3e38f, best2B = -3e38f;
    int   bkA = 0, bkB = 0;

    const float* Kbase = g_Kh + (size_t)h * N_NODES * 64;
    const int keyld = tid & 63;                // key this thread loads
    const int kb    = l4 * 2;

    for (int t = 0; t < 64; t++) {
        __syncthreads();
        // ---- load K tile (64 keys x 64 d), tf32-round, XOR-swizzled store ----
        {
            const float* src = Kbase + (size_t)(t * 64 + keyld) * 64;
            const int xz = (keyld & 7) << 2;
#pragma unroll
            for (int it = 0; it < 8; it++) {
                const int d0 = (it * 2 + (tid >> 6)) * 4;
                float4 v = *(const float4*)&src[d0];
                v.x = tf32f(v.x); v.y = tf32f(v.y);
                v.z = tf32f(v.z); v.w = tf32f(v.w);
                *(float4*)&sK[keyld * 64 + (d0 ^ xz)] = v;
            }
        }
        __syncthreads();

        // ---- MMA: 8 key-frags x 8 k-steps ----
        float acc[8][4];
#pragma unroll
        for (int nf = 0; nf < 8; nf++) {
            acc[nf][0] = 0.f; acc[nf][1] = 0.f;
            acc[nf][2] = 0.f; acc[nf][3] = 0.f;
            const uint32_t* krow = (const uint32_t*)&sK[(nf * 8 + g) * 64];
            const int x = g << 2;
#pragma unroll
            for (int s = 0; s < 8; s++) {
                const uint32_t b0 = krow[(s * 8 + l4) ^ x];
                const uint32_t b1 = krow[(s * 8 + 4 + l4) ^ x];
                mma8(acc[nf], a[s], b0, b1);
            }
        }

        // ---- masked online top-2 argmax ----
        const unsigned w00 = g_adjbits[(t * 2 + 0) * N_NODES + qA] >> kb;
        const unsigned w01 = g_adjbits[(t * 2 + 1) * N_NODES + qA] >> kb;
        const unsigned w10 = g_adjbits[(t * 2 + 0) * N_NODES + qB] >> kb;
        const unsigned w11 = g_adjbits[(t * 2 + 1) * N_NODES + qB] >> kb;
        const int kidx0 = t * 64 + kb;
#pragma unroll
        for (int nf = 0; nf < 8; nf++) {
            const unsigned wA = (nf < 4) ? w00 : w01;
            const unsigned wB = (nf < 4) ? w10 : w11;
            const int sh = (nf & 3) * 8;
#pragma unroll
            for (int c = 0; c < 4; c++) {
                const int ki = kidx0 + nf * 8 + (c & 1);
                if (c < 2) {
                    const float v = ((wA >> (sh + (c & 1))) & 1u) ? acc[nf][c] : -3e38f;
                    best2A = fmaxf(best2A, fminf(bestA, v));
                    if (v > bestA) { bestA = v; bkA = ki; }
                } else {
                    const float v = ((wB >> (sh + (c & 1))) & 1u) ? acc[nf][c] : -3e38f;
                    best2B = fmaxf(best2B, fminf(bestB, v));
                    if (v > bestB) { bestB = v; bkB = ki; }
                }
            }
        }
    }

    // ---- reduce across the 4 lanes of each quad (same q rows) ----
#pragma unroll
    for (int off = 1; off < 4; off <<= 1) {
        float ob  = __shfl_xor_sync(0xffffffffu, bestA, off);
        int   obk = __shfl_xor_sync(0xffffffffu, bkA,  off);
        float ob2 = __shfl_xor_sync(0xffffffffu, best2A, off);
        best2A = fmaxf(fmaxf(best2A, ob2), fminf(bestA, ob));
        if (ob > bestA || (ob == bestA && obk < bkA)) { bestA = ob; bkA = obk; }

        ob  = __shfl_xor_sync(0xffffffffu, bestB, off);
        obk = __shfl_xor_sync(0xffffffffu, bkB,  off);
        ob2 = __shfl_xor_sync(0xffffffffu, best2B, off);
        best2B = fmaxf(fmaxf(best2B, ob2), fminf(bestB, ob));
        if (ob > bestB || (ob == bestB && obk < bkB)) { bestB = ob; bkB = obk; }
    }

    if (l4 == 0) {
        const int hqA = h * N_NODES + qA;
        const int hqB = h * N_NODES + qB;
        g_argmax[hqA] = bkA;
        g_argmax[hqB] = bkB;
        if (bestA - best2A < BAND) {
            const int s = atomicAdd(&g_fixcount, 1);
            g_fixlist[s] = hqA;
        }
        if (bestB - best2B < BAND) {
            const int s = atomicAdd(&g_fixcount, 1);
            g_fixlist[s] = hqB;
        }
    }
}

// ============================================================================
// Pass 2: exact fp32 re-argmax of flagged rows (block per row).
// ============================================================================
__global__ __launch_bounds__(256) void rescan() {
    __shared__ float s_best[8];
    __shared__ int   s_bk[8];
    const int nfix = g_fixcount;
    const int tid = threadIdx.x, lane = tid & 31, wrp = tid >> 5;

    for (int i = blockIdx.x; i < nfix; i += gridDim.x) {
        const int hq = g_fixlist[i];
        const int h = hq >> 12, q = hq & (N_NODES - 1);
        const float* Qr = g_Qh + ((size_t)h * N_NODES + q) * 64;
        float qv[64];
#pragma unroll
        for (int j = 0; j < 16; j++) {
            float4 v = *(const float4*)&Qr[j * 4];
            qv[j*4] = v.x; qv[j*4+1] = v.y; qv[j*4+2] = v.z; qv[j*4+3] = v.w;
        }

        float best = -3e38f;
        int   bk   = 1 << 30;
        for (int k = tid; k < N_NODES; k += 256) {
            const unsigned wd = g_adjbits[(k >> 5) * N_NODES + q];
            if ((wd >> (k & 31)) & 1u) {
                const float* Kr = g_Kh + ((size_t)h * N_NODES + k) * 64;
                float d = 0.f;
#pragma unroll
                for (int j = 0; j < 16; j++) {
                    float4 v = *(const float4*)&Kr[j * 4];
                    d += qv[j*4] * v.x + qv[j*4+1] * v.y
                       + qv[j*4+2] * v.z + qv[j*4+3] * v.w;
                }
                if (d > best || (d == best && k < bk)) { best = d; bk = k; }
            }
        }
#pragma unroll
        for (int off = 16; off > 0; off >>= 1) {
            float ob  = __shfl_xor_sync(0xffffffffu, best, off);
            int   obk = __shfl_xor_sync(0xffffffffu, bk, off);
            if (ob > best || (ob == best && obk < bk)) { best = ob; bk = obk; }
        }
        if (lane == 0) { s_best[wrp] = best; s_bk[wrp] = bk; }
        __syncthreads();
        if (tid == 0) {
            float b = s_best[0]; int k = s_bk[0];
#pragma unroll
            for (int j = 1; j < 8; j++)
                if (s_best[j] > b || (s_best[j] == b && s_bk[j] < k)) {
                    b = s_best[j]; k = s_bk[j];
                }
            g_argmax[hq] = k;
        }
        __syncthreads();
    }
}

// ============================================================================
// out[q, h*64+d] = V[argmax(h,q), h*64+d] / HEADS
// ============================================================================
__global__ __launch_bounds__(256) void gather_out(float* __restrict__ out) {
    const int idx = blockIdx.x * blockDim.x + threadIdx.x;
    const int q   = idx >> 7;
    const int c4  = idx & 127;
    const int h   = c4 >> 4;
    const int k   = g_argmax[h * N_NODES + q];
    float4 t = *(const float4*)&g_V[(size_t)k * 512 + c4 * 4];
    float4 v = make_float4(t.x * 0.125f, t.y * 0.125f, t.z * 0.125f, t.w * 0.125f);
    *(float4*)&out[(size_t)idx * 4] = v;
}

// ============================================================================
extern "C" void kernel_launch(void* const* d_in, const int* in_sizes, int n_in,
                              void* d_out, int out_size)
{
    const float* x   = (const float*)d_in[0];
    const int*   adj = (const int*)d_in[1];
    const float* WQ  = (const float*)d_in[2];
    const float* WK  = (const float*)d_in[3];
    const float* WV  = (const float*)d_in[4];
    float* out = (float*)d_out;

    cudaFuncSetAttribute(qkv_gemm,
                         cudaFuncAttributeMaxDynamicSharedMemorySize, QKV_SMEM);

    dim3 tb(32, 8);
    transpose_x<<<dim3(IN_FEAT / 32, N_NODES / 32), tb>>>(x);
    transpose_w<<<dim3(IN_FEAT / 32, 512 / 32, 3), tb>>>(WQ, WK, WV);
    adj_to_bits<<<N_NODES / 8, 256>>>(adj);

    qkv_gemm<<<dim3(E3 / 128, N_NODES / 128), 512, QKV_SMEM>>>();

    score_mma<<<dim3(N_NODES / 64, HEADS), 128>>>();

    rescan<<<2048, 256>>>();

    gather_out<<<(N_NODES * 512 / 4) / 256, 256>>>(out);
}